// round 1
// baseline (speedup 1.0000x reference)
#include <cuda_runtime.h>
#include <cstdint>

// ============================================================================
// VAE_Decoder_6030134084248 : 4-layer QKeras-quantized MLP
//   x[8192,128] -> (W0,b0)[128,1024] -> qrelu6 -> (W1,b1)[1024,2048] -> qrelu6
//   -> (W2,b2)[2048,4096] -> qrelu6 -> (W3,b3)[4096,4096] -> fp32 out
//
// Exact-integer formulation:
//   wq = clip(rint(W*32), -32, 31)        (6-bit signed code k, value k/32)
//   bq = clip(rint(b*32), -32, 31) = m    (value m/32)
//   act codes a in {0..63}                (value a/64)
//   layer i>0:  acc = sum(a*k) int32 (exact);  s = acc + 64*m
//               next code = clip(round_half_even(s/32), 0, 63)
//   layer 3:    out = acc/2048 + m/32     (exact in fp32)
// This matches the jax fp32 reference bit-exactly for layers 1..3.
// ============================================================================

static const int M = 8192;

// ---- scratch (device globals: no allocation allowed) ----
__device__ float   g_w0q[128 * 1024];           // layer0 weights, value k/32
__device__ int8_t  g_w1t[2048l * 1024];         // [N=2048][K=1024] codes
__device__ int8_t  g_w2t[4096l * 2048];         // [N=4096][K=2048]
__device__ int8_t  g_w3t[4096l * 4096];         // [N=4096][K=4096]
__device__ int     g_b0q[1024];
__device__ int     g_b1q[2048];
__device__ int     g_b2q[4096];
__device__ float   g_b3q[4096];
__device__ uint8_t g_a0[8192l * 1024];
__device__ uint8_t g_a1[8192l * 2048];
__device__ uint8_t g_a2[8192l * 4096];

__device__ __forceinline__ float qcode(float x) {
    // clip(round_half_even(x*32), -32, 31)  -- the integer code as float
    float c = rintf(x * 32.0f);
    return fminf(fmaxf(c, -32.0f), 31.0f);
}

// ---- quantizers ----------------------------------------------------------
__global__ void k_quant_w0(const float* __restrict__ W, float* __restrict__ out) {
    int i = blockIdx.x * blockDim.x + threadIdx.x;
    if (i < 128 * 1024) out[i] = qcode(W[i]) * (1.0f / 32.0f);
}

__global__ void k_quant_bias_int(const float* __restrict__ b, int* __restrict__ out, int n) {
    int i = blockIdx.x * blockDim.x + threadIdx.x;
    if (i < n) out[i] = (int)qcode(b[i]);
}

__global__ void k_quant_b3(const float* __restrict__ b, float* __restrict__ out, int n) {
    int i = blockIdx.x * blockDim.x + threadIdx.x;
    if (i < n) out[i] = qcode(b[i]) * (1.0f / 32.0f);
}

// W[K,N] row-major -> Bt[N,K] int8 codes (transpose-quantize, 32x32 tiles)
__global__ void k_quant_wT(const float* __restrict__ W, int8_t* __restrict__ Bt,
                           int K, int N) {
    __shared__ int8_t t[32][33];
    int n0 = blockIdx.x * 32, k0 = blockIdx.y * 32;
    int tx = threadIdx.x, ty = threadIdx.y;   // 32 x 8
#pragma unroll
    for (int r = ty; r < 32; r += 8)
        t[r][tx] = (int8_t)qcode(W[(size_t)(k0 + r) * N + n0 + tx]);
    __syncthreads();
#pragma unroll
    for (int r = ty; r < 32; r += 8)
        Bt[(size_t)(n0 + r) * K + k0 + tx] = t[tx][r];
}

// ---- layer 0: fp32 GEMM 8192x128x1024, fused bias + quantized_relu -------
__global__ __launch_bounds__(256)
void k_gemm_l0(const float* __restrict__ X, const float* __restrict__ Bq,
               const int* __restrict__ bias, uint8_t* __restrict__ Out) {
    __shared__ float As[32][65];   // [k][m], pad 65 -> conflict-free stores
    __shared__ float Bs[32][64];   // [k][n]
    int tid = threadIdx.x;
    int tx = tid & 15, ty = tid >> 4;
    int m0 = blockIdx.y * 64, n0 = blockIdx.x * 64;
    float acc[4][4] = {};

    for (int k0 = 0; k0 < 128; k0 += 32) {
        {   // A tile: 64 rows x 32 floats, transposed store into [k][m]
            int r = tid >> 3, c = tid & 7;
#pragma unroll
            for (int p = 0; p < 2; p++) {
                float4 v = *(const float4*)(X + (size_t)(m0 + r + p * 32) * 128 + k0 + c * 4);
                int rr = r + p * 32;
                As[c * 4 + 0][rr] = v.x; As[c * 4 + 1][rr] = v.y;
                As[c * 4 + 2][rr] = v.z; As[c * 4 + 3][rr] = v.w;
            }
        }
        {   // B tile: 32 rows x 64 floats
            int kr = tid >> 4, cx = tid & 15;
#pragma unroll
            for (int p = 0; p < 2; p++) {
                float4 v = *(const float4*)(Bq + (size_t)(k0 + kr + p * 16) * 1024 + n0 + cx * 4);
                *(float4*)&Bs[kr + p * 16][cx * 4] = v;
            }
        }
        __syncthreads();
#pragma unroll
        for (int k = 0; k < 32; k++) {
            float a[4], b[4];
#pragma unroll
            for (int i = 0; i < 4; i++) a[i] = As[k][i * 16 + ty];
#pragma unroll
            for (int j = 0; j < 4; j++) b[j] = Bs[k][j * 16 + tx];
#pragma unroll
            for (int i = 0; i < 4; i++)
#pragma unroll
                for (int j = 0; j < 4; j++) acc[i][j] = fmaf(a[i], b[j], acc[i][j]);
        }
        __syncthreads();
    }
#pragma unroll
    for (int j = 0; j < 4; j++) {
        int n = n0 + j * 16 + tx;
        float bm2 = 2.0f * (float)bias[n];   // (m/32)*64
#pragma unroll
        for (int i = 0; i < 4; i++) {
            int m = m0 + i * 16 + ty;
            float p = acc[i][j] * 64.0f + bm2;     // p = h*64
            float q = rintf(p);                     // half-to-even
            q = fminf(fmaxf(q, 0.0f), 63.0f);
            Out[(size_t)m * 1024 + n] = (uint8_t)q;
        }
    }
}

// ---- layers 1..3: int8 dp4a GEMM, 128x128x32B tiles, 8x8 per thread ------
template <int K, bool LAST>
__global__ __launch_bounds__(256, 2)
void k_gemm_i8(const uint8_t* __restrict__ A,   // [M,K] codes 0..63
               const int8_t* __restrict__ Bt,   // [N,K] codes -32..31
               const int* __restrict__ bq,      // bias codes (if !LAST)
               const float* __restrict__ bf,    // bias value  (if LAST)
               uint8_t* __restrict__ Cq, float* __restrict__ Cf, int N) {
    __shared__ uint32_t As[8][128];   // [kword][m]
    __shared__ uint32_t Bs[8][128];   // [kword][n]
    int tid = threadIdx.x;
    int tx = tid & 15, ty = tid >> 4;
    int n0 = blockIdx.x * 128, m0 = blockIdx.y * 128;
    int acc[8][8] = {};

    int r = tid >> 1, half = tid & 1;
    const uint8_t* Arow = A + (size_t)(m0 + r) * K + half * 16;
    const int8_t*  Brow = Bt + (size_t)(n0 + r) * K + half * 16;

    for (int k0 = 0; k0 < K; k0 += 32) {
        uint4 av = *(const uint4*)(Arow + k0);
        uint4 bv = *(const uint4*)(Brow + k0);
        __syncthreads();
        As[half * 4 + 0][r] = av.x; As[half * 4 + 1][r] = av.y;
        As[half * 4 + 2][r] = av.z; As[half * 4 + 3][r] = av.w;
        Bs[half * 4 + 0][r] = bv.x; Bs[half * 4 + 1][r] = bv.y;
        Bs[half * 4 + 2][r] = bv.z; Bs[half * 4 + 3][r] = bv.w;
        __syncthreads();
#pragma unroll
        for (int w = 0; w < 8; w++) {
            uint32_t a[8], b[8];
#pragma unroll
            for (int i = 0; i < 8; i++) a[i] = As[w][i * 16 + ty];
#pragma unroll
            for (int j = 0; j < 8; j++) b[j] = Bs[w][j * 16 + tx];
#pragma unroll
            for (int i = 0; i < 8; i++)
#pragma unroll
                for (int j = 0; j < 8; j++)
                    acc[i][j] = __dp4a((int)a[i], (int)b[j], acc[i][j]);
        }
    }

    if (!LAST) {
#pragma unroll
        for (int j = 0; j < 8; j++) {
            int n = n0 + j * 16 + tx;
            int mb = bq[n] * 64;
#pragma unroll
            for (int i = 0; i < 8; i++) {
                int m = m0 + i * 16 + ty;
                int s = acc[i][j] + mb;           // p*32, exact
                int q = s >> 5;                   // floor
                int rr = s & 31;
                q += (rr > 16) ? 1 : ((rr == 16) ? (q & 1) : 0);  // half-to-even
                q = min(max(q, 0), 63);
                Cq[(size_t)m * N + n] = (uint8_t)q;
            }
        }
    } else {
#pragma unroll
        for (int j = 0; j < 8; j++) {
            int n = n0 + j * 16 + tx;
            float bb = bf[n];
#pragma unroll
            for (int i = 0; i < 8; i++) {
                int m = m0 + i * 16 + ty;
                Cf[(size_t)m * N + n] = (float)acc[i][j] * (1.0f / 2048.0f) + bb;
            }
        }
    }
}

// ---- launch --------------------------------------------------------------
extern "C" void kernel_launch(void* const* d_in, const int* in_sizes, int n_in,
                              void* d_out, int out_size) {
    const float* x  = (const float*)d_in[0];
    const float* W0 = (const float*)d_in[1]; const float* b0 = (const float*)d_in[2];
    const float* W1 = (const float*)d_in[3]; const float* b1 = (const float*)d_in[4];
    const float* W2 = (const float*)d_in[5]; const float* b2 = (const float*)d_in[6];
    const float* W3 = (const float*)d_in[7]; const float* b3 = (const float*)d_in[8];

    float *w0q, *b3q; int8_t *w1t, *w2t, *w3t; int *b0q, *b1q, *b2q;
    uint8_t *a0, *a1, *a2;
    cudaGetSymbolAddress((void**)&w0q, g_w0q);
    cudaGetSymbolAddress((void**)&w1t, g_w1t);
    cudaGetSymbolAddress((void**)&w2t, g_w2t);
    cudaGetSymbolAddress((void**)&w3t, g_w3t);
    cudaGetSymbolAddress((void**)&b0q, g_b0q);
    cudaGetSymbolAddress((void**)&b1q, g_b1q);
    cudaGetSymbolAddress((void**)&b2q, g_b2q);
    cudaGetSymbolAddress((void**)&b3q, g_b3q);
    cudaGetSymbolAddress((void**)&a0,  g_a0);
    cudaGetSymbolAddress((void**)&a1,  g_a1);
    cudaGetSymbolAddress((void**)&a2,  g_a2);

    // quantize weights / biases
    k_quant_w0<<<512, 256>>>(W0, w0q);
    k_quant_bias_int<<<4, 256>>>(b0, b0q, 1024);
    k_quant_bias_int<<<8, 256>>>(b1, b1q, 2048);
    k_quant_bias_int<<<16, 256>>>(b2, b2q, 4096);
    k_quant_b3<<<16, 256>>>(b3, b3q, 4096);
    {
        dim3 blk(32, 8);
        k_quant_wT<<<dim3(2048 / 32, 1024 / 32), blk>>>(W1, w1t, 1024, 2048);
        k_quant_wT<<<dim3(4096 / 32, 2048 / 32), blk>>>(W2, w2t, 2048, 4096);
        k_quant_wT<<<dim3(4096 / 32, 4096 / 32), blk>>>(W3, w3t, 4096, 4096);
    }

    // layer 0: fp32 GEMM + qrelu  -> a0
    k_gemm_l0<<<dim3(1024 / 64, M / 64), 256>>>(x, w0q, b0q, a0);

    // layers 1..3: exact integer GEMMs
    k_gemm_i8<1024, false><<<dim3(2048 / 128, M / 128), 256>>>(a0, w1t, b1q, nullptr, a1, nullptr, 2048);
    k_gemm_i8<2048, false><<<dim3(4096 / 128, M / 128), 256>>>(a1, w2t, b2q, nullptr, a2, nullptr, 4096);
    k_gemm_i8<4096, true ><<<dim3(4096 / 128, M / 128), 256>>>(a2, w3t, nullptr, b3q, nullptr, (float*)d_out, 4096);
}

// round 2
// speedup vs baseline: 1.2094x; 1.2094x over previous
#include <cuda_runtime.h>
#include <cstdint>

// ============================================================================
// VAE_Decoder_6030134084248 : 4-layer QKeras-quantized MLP (exact-integer form)
//   Layers 1..3 on tensor cores: mma.sync m16n8k32 u8.s8.s32 (bit-exact).
// ============================================================================

static const int M = 8192;

// ---- scratch (device globals: no allocation allowed) ----
__device__ __align__(128) float   g_w0q[128 * 1024];
__device__ __align__(128) int8_t  g_w1t[2048l * 1024];   // [N][K] codes
__device__ __align__(128) int8_t  g_w2t[4096l * 2048];
__device__ __align__(128) int8_t  g_w3t[4096l * 4096];
__device__ int     g_b0q[1024];
__device__ int     g_b1q[2048];
__device__ int     g_b2q[4096];
__device__ float   g_b3q[4096];
__device__ __align__(128) uint8_t g_a0[8192l * 1024];
__device__ __align__(128) uint8_t g_a1[8192l * 2048];
__device__ __align__(128) uint8_t g_a2[8192l * 4096];

__device__ __forceinline__ float qcode(float x) {
    float c = rintf(x * 32.0f);
    return fminf(fmaxf(c, -32.0f), 31.0f);
}

// ---- quantizers ----------------------------------------------------------
__global__ void k_quant_w0(const float* __restrict__ W, float* __restrict__ out) {
    int i = blockIdx.x * blockDim.x + threadIdx.x;
    if (i < 128 * 1024) out[i] = qcode(W[i]) * (1.0f / 32.0f);
}
__global__ void k_quant_bias_int(const float* __restrict__ b, int* __restrict__ out, int n) {
    int i = blockIdx.x * blockDim.x + threadIdx.x;
    if (i < n) out[i] = (int)qcode(b[i]);
}
__global__ void k_quant_b3(const float* __restrict__ b, float* __restrict__ out, int n) {
    int i = blockIdx.x * blockDim.x + threadIdx.x;
    if (i < n) out[i] = qcode(b[i]) * (1.0f / 32.0f);
}
__global__ void k_quant_wT(const float* __restrict__ W, int8_t* __restrict__ Bt,
                           int K, int N) {
    __shared__ int8_t t[32][33];
    int n0 = blockIdx.x * 32, k0 = blockIdx.y * 32;
    int tx = threadIdx.x, ty = threadIdx.y;   // 32 x 8
#pragma unroll
    for (int r = ty; r < 32; r += 8)
        t[r][tx] = (int8_t)qcode(W[(size_t)(k0 + r) * N + n0 + tx]);
    __syncthreads();
#pragma unroll
    for (int r = ty; r < 32; r += 8)
        Bt[(size_t)(n0 + r) * K + k0 + tx] = t[tx][r];
}

// ---- layer 0: fp32 SIMT GEMM 8192x128x1024 + bias + qrelu ----------------
__global__ __launch_bounds__(256)
void k_gemm_l0(const float* __restrict__ X, const float* __restrict__ Bq,
               const int* __restrict__ bias, uint8_t* __restrict__ Out) {
    __shared__ float As[32][65];
    __shared__ float Bs[32][64];
    int tid = threadIdx.x;
    int tx = tid & 15, ty = tid >> 4;
    int m0 = blockIdx.y * 64, n0 = blockIdx.x * 64;
    float acc[4][4] = {};
    for (int k0 = 0; k0 < 128; k0 += 32) {
        {
            int r = tid >> 3, c = tid & 7;
#pragma unroll
            for (int p = 0; p < 2; p++) {
                float4 v = *(const float4*)(X + (size_t)(m0 + r + p * 32) * 128 + k0 + c * 4);
                int rr = r + p * 32;
                As[c * 4 + 0][rr] = v.x; As[c * 4 + 1][rr] = v.y;
                As[c * 4 + 2][rr] = v.z; As[c * 4 + 3][rr] = v.w;
            }
        }
        {
            int kr = tid >> 4, cx = tid & 15;
#pragma unroll
            for (int p = 0; p < 2; p++) {
                float4 v = *(const float4*)(Bq + (size_t)(k0 + kr + p * 16) * 1024 + n0 + cx * 4);
                *(float4*)&Bs[kr + p * 16][cx * 4] = v;
            }
        }
        __syncthreads();
#pragma unroll
        for (int k = 0; k < 32; k++) {
            float a[4], b[4];
#pragma unroll
            for (int i = 0; i < 4; i++) a[i] = As[k][i * 16 + ty];
#pragma unroll
            for (int j = 0; j < 4; j++) b[j] = Bs[k][j * 16 + tx];
#pragma unroll
            for (int i = 0; i < 4; i++)
#pragma unroll
                for (int j = 0; j < 4; j++) acc[i][j] = fmaf(a[i], b[j], acc[i][j]);
        }
        __syncthreads();
    }
#pragma unroll
    for (int j = 0; j < 4; j++) {
        int n = n0 + j * 16 + tx;
        float bm2 = 2.0f * (float)bias[n];
#pragma unroll
        for (int i = 0; i < 4; i++) {
            int m = m0 + i * 16 + ty;
            float p = acc[i][j] * 64.0f + bm2;
            float q = rintf(p);
            q = fminf(fmaxf(q, 0.0f), 63.0f);
            Out[(size_t)m * 1024 + n] = (uint8_t)q;
        }
    }
}

// ---- tensor-core int8 GEMM (layers 1..3) ---------------------------------
__device__ __forceinline__ void cp16(uint32_t dst, const void* src) {
    asm volatile("cp.async.cg.shared.global [%0], [%1], 16;\n" :: "r"(dst), "l"(src));
}
__device__ __forceinline__ void cp_commit() { asm volatile("cp.async.commit_group;\n"); }
template <int N_>
__device__ __forceinline__ void cp_wait() { asm volatile("cp.async.wait_group %0;\n" :: "n"(N_)); }

__device__ __forceinline__ void ldsm4(uint32_t& r0, uint32_t& r1, uint32_t& r2, uint32_t& r3,
                                      uint32_t addr) {
    asm volatile("ldmatrix.sync.aligned.m8n8.x4.shared.b16 {%0,%1,%2,%3}, [%4];\n"
                 : "=r"(r0), "=r"(r1), "=r"(r2), "=r"(r3) : "r"(addr));
}
__device__ __forceinline__ void imma(int* c, const uint32_t* a, const uint32_t* b) {
    asm volatile(
        "mma.sync.aligned.m16n8k32.row.col.s32.u8.s8.s32 "
        "{%0,%1,%2,%3}, {%4,%5,%6,%7}, {%8,%9}, {%0,%1,%2,%3};\n"
        : "+r"(c[0]), "+r"(c[1]), "+r"(c[2]), "+r"(c[3])
        : "r"(a[0]), "r"(a[1]), "r"(a[2]), "r"(a[3]), "r"(b[0]), "r"(b[1]));
}

// swizzled byte offset within a [rows][64B] tile: chunk c in 0..3 (16B units)
__device__ __forceinline__ uint32_t swz(int r, int c) {
    return (uint32_t)(r * 64 + ((c ^ ((r >> 1) & 3)) << 4));
}

template <int K, bool LAST>
__global__ __launch_bounds__(256, 2)
void k_imma(const uint8_t* __restrict__ A,    // [M][K] codes 0..63
            const int8_t* __restrict__ Bt,    // [N][K] codes -32..31
            const int* __restrict__ bq, const float* __restrict__ bf,
            uint8_t* __restrict__ Cq, float* __restrict__ Cf, int N) {
    __shared__ __align__(16) uint8_t sA[2][128 * 64];
    __shared__ __align__(16) uint8_t sB[2][128 * 64];

    const int tid = threadIdx.x;
    const int wid = tid >> 5, lane = tid & 31;
    const int wm = wid >> 2, wn = wid & 3;      // 2 x 4 warp grid
    const int g = lane >> 2, tig = lane & 3;
    const int m0 = blockIdx.y * 128, n0 = blockIdx.x * 128;

    // --- global->shared load descriptors: each thread moves 2 A + 2 B chunks
    const int lr = tid >> 2;       // row 0..63
    const int lc = tid & 3;        // 16B chunk 0..3
    const uint8_t* gA = A + (size_t)(m0 + lr) * K + lc * 16;
    const int8_t*  gB = Bt + (size_t)(n0 + lr) * K + lc * 16;
    const size_t gStep = (size_t)64 * K;
    const uint32_t dA = swz(lr, lc);            // same swizzle both halves
    uint32_t sAb = (uint32_t)__cvta_generic_to_shared(&sA[0][0]);
    uint32_t sBb = (uint32_t)__cvta_generic_to_shared(&sB[0][0]);

    // --- per-lane ldmatrix offsets (stage-relative)
    const int rl  = (lane & 7) + 8 * ((lane >> 3) & 1);
    const int ch  = (lane >> 4) & 1;
    const int rlA = wm * 64 + rl;
    const int rlB = wn * 32 + rl;
    uint32_t offA[2], offB[2];
#pragma unroll
    for (int ks = 0; ks < 2; ks++) {
        offA[ks] = swz(rlA, 2 * ks + ch);
        offB[ks] = swz(rlB, 2 * ks + ch);
    }

    int acc[4][4][4] = {};
    const int NK = K / 64;

    auto issue = [&](int kiter, int stage) {
        uint32_t a_s = sAb + stage * (128 * 64);
        uint32_t b_s = sBb + stage * (128 * 64);
        size_t go = (size_t)kiter * 64;
#pragma unroll
        for (int p = 0; p < 2; p++) {
            cp16(a_s + dA + p * (64 * 64), gA + go + p * gStep);
            cp16(b_s + dA + p * (64 * 64), gB + go + p * gStep);
        }
    };

    issue(0, 0); cp_commit();
    issue(1, 1); cp_commit();

    for (int ki = 0; ki < NK; ki++) {
        const int st = ki & 1;
        cp_wait<1>();
        __syncthreads();
        uint32_t a_s = sAb + st * (128 * 64);
        uint32_t b_s = sBb + st * (128 * 64);
#pragma unroll
        for (int ks = 0; ks < 2; ks++) {
            uint32_t a[4][4], b[4][2];
#pragma unroll
            for (int mi = 0; mi < 4; mi++)
                ldsm4(a[mi][0], a[mi][1], a[mi][2], a[mi][3],
                      a_s + offA[ks] + mi * 1024);
#pragma unroll
            for (int np = 0; np < 2; np++) {
                uint32_t r0, r1, r2, r3;
                ldsm4(r0, r1, r2, r3, b_s + offB[ks] + np * 1024);
                b[2 * np + 0][0] = r0; b[2 * np + 0][1] = r2;
                b[2 * np + 1][0] = r1; b[2 * np + 1][1] = r3;
            }
#pragma unroll
            for (int mi = 0; mi < 4; mi++)
#pragma unroll
                for (int nj = 0; nj < 4; nj++)
                    imma(acc[mi][nj], a[mi], b[nj]);
        }
        __syncthreads();
        if (ki + 2 < NK) issue(ki + 2, st);
        cp_commit();
    }

    // --- epilogue (exact integer requant / final fp32) ---
#pragma unroll
    for (int nj = 0; nj < 4; nj++) {
        int n = n0 + wn * 32 + nj * 8 + 2 * tig;
        if (!LAST) {
            int mb0 = bq[n] * 64, mb1 = bq[n + 1] * 64;
#pragma unroll
            for (int mi = 0; mi < 4; mi++) {
#pragma unroll
                for (int h = 0; h < 2; h++) {
                    int m = m0 + wm * 64 + mi * 16 + g + 8 * h;
                    int s0 = acc[mi][nj][2 * h + 0] + mb0;
                    int s1 = acc[mi][nj][2 * h + 1] + mb1;
                    int q0 = s0 >> 5, r0 = s0 & 31;
                    q0 += (r0 > 16) ? 1 : ((r0 == 16) ? (q0 & 1) : 0);
                    q0 = min(max(q0, 0), 63);
                    int q1 = s1 >> 5, r1 = s1 & 31;
                    q1 += (r1 > 16) ? 1 : ((r1 == 16) ? (q1 & 1) : 0);
                    q1 = min(max(q1, 0), 63);
                    *(uint16_t*)&Cq[(size_t)m * N + n] =
                        (uint16_t)(q0 | (q1 << 8));
                }
            }
        } else {
            float bb0 = bf[n], bb1 = bf[n + 1];
#pragma unroll
            for (int mi = 0; mi < 4; mi++) {
#pragma unroll
                for (int h = 0; h < 2; h++) {
                    int m = m0 + wm * 64 + mi * 16 + g + 8 * h;
                    float2 v;
                    v.x = (float)acc[mi][nj][2 * h + 0] * (1.0f / 2048.0f) + bb0;
                    v.y = (float)acc[mi][nj][2 * h + 1] * (1.0f / 2048.0f) + bb1;
                    *(float2*)&Cf[(size_t)m * N + n] = v;
                }
            }
        }
    }
}

// ---- launch --------------------------------------------------------------
extern "C" void kernel_launch(void* const* d_in, const int* in_sizes, int n_in,
                              void* d_out, int out_size) {
    const float* x  = (const float*)d_in[0];
    const float* W0 = (const float*)d_in[1]; const float* b0 = (const float*)d_in[2];
    const float* W1 = (const float*)d_in[3]; const float* b1 = (const float*)d_in[4];
    const float* W2 = (const float*)d_in[5]; const float* b2 = (const float*)d_in[6];
    const float* W3 = (const float*)d_in[7]; const float* b3 = (const float*)d_in[8];

    float *w0q, *b3q; int8_t *w1t, *w2t, *w3t; int *b0q, *b1q, *b2q;
    uint8_t *a0, *a1, *a2;
    cudaGetSymbolAddress((void**)&w0q, g_w0q);
    cudaGetSymbolAddress((void**)&w1t, g_w1t);
    cudaGetSymbolAddress((void**)&w2t, g_w2t);
    cudaGetSymbolAddress((void**)&w3t, g_w3t);
    cudaGetSymbolAddress((void**)&b0q, g_b0q);
    cudaGetSymbolAddress((void**)&b1q, g_b1q);
    cudaGetSymbolAddress((void**)&b2q, g_b2q);
    cudaGetSymbolAddress((void**)&b3q, g_b3q);
    cudaGetSymbolAddress((void**)&a0,  g_a0);
    cudaGetSymbolAddress((void**)&a1,  g_a1);
    cudaGetSymbolAddress((void**)&a2,  g_a2);

    k_quant_w0<<<512, 256>>>(W0, w0q);
    k_quant_bias_int<<<4, 256>>>(b0, b0q, 1024);
    k_quant_bias_int<<<8, 256>>>(b1, b1q, 2048);
    k_quant_bias_int<<<16, 256>>>(b2, b2q, 4096);
    k_quant_b3<<<16, 256>>>(b3, b3q, 4096);
    {
        dim3 blk(32, 8);
        k_quant_wT<<<dim3(2048 / 32, 1024 / 32), blk>>>(W1, w1t, 1024, 2048);
        k_quant_wT<<<dim3(4096 / 32, 2048 / 32), blk>>>(W2, w2t, 2048, 4096);
        k_quant_wT<<<dim3(4096 / 32, 4096 / 32), blk>>>(W3, w3t, 4096, 4096);
    }

    k_gemm_l0<<<dim3(1024 / 64, M / 64), 256>>>(x, w0q, b0q, a0);

    k_imma<1024, false><<<dim3(2048 / 128, M / 128), 256>>>(a0, w1t, b1q, nullptr, a1, nullptr, 2048);
    k_imma<2048, false><<<dim3(4096 / 128, M / 128), 256>>>(a1, w2t, b2q, nullptr, a2, nullptr, 4096);
    k_imma<4096, true ><<<dim3(4096 / 128, M / 128), 256>>>(a2, w3t, nullptr, b3q, nullptr, (float*)d_out, 4096);
}